// round 5
// baseline (speedup 1.0000x reference)
#include <cuda_runtime.h>

#define B 16
#define L 2048
#define EPS 1e-8f
#define ROWS_PER_BLK 16
#define THREADS 512
#define TILES_PER_BATCH (L / ROWS_PER_BLK)       // 128
#define TOTAL_TILES (B * TILES_PER_BATCH)        // 2048
#define GRID 296                                  // 2 blocks per SM (148 SMs)
#define CHUNK ((TOTAL_TILES + GRID - 1) / GRID)   // 7

// Persistent fused GAF: out[b][i][j] = s_i*s_j - r_i*r_j,
// s = clipped minmax scale of x (= cos(arccos)), r = sqrt(1-s^2) (= sin).
// 296 resident blocks; each owns a contiguous batch-major chunk of 16-row
// tiles, re-running the per-batch prep only when its batch changes.
__global__ void __launch_bounds__(THREADS) gaf_persist_kernel(
    const float* __restrict__ x, float* __restrict__ out) {
    const int t    = threadIdx.x;
    const int lane = t & 31;
    const int wid  = t >> 5;                 // 16 warps

    __shared__ float red_min[16], red_max[16];
    __shared__ float sh_mn, sh_inv;
    __shared__ float sh_si[ROWS_PER_BLK], sh_ri[ROWS_PER_BLK];

    const int tile_start = blockIdx.x * CHUNK;
    const int tile_end   = min(tile_start + CHUNK, TOTAL_TILES);

    int cur_b = -1;
    float4 s4, r4;                            // this thread's 4 j-values

    for (int tile = tile_start; tile < tile_end; tile++) {
        const int b  = tile >> 7;             // tile / TILES_PER_BATCH
        const int i0 = (tile & (TILES_PER_BATCH - 1)) * ROWS_PER_BLK;

        if (b != cur_b) {
            cur_b = b;
            __syncthreads();                  // protect smem reuse across tiles

            // ---- prep: min/max reduce + s,r for own 4 elems ----
            const float4 v = reinterpret_cast<const float4*>(x + b * L)[t];
            float vmin = fminf(fminf(v.x, v.y), fminf(v.z, v.w));
            float vmax = fmaxf(fmaxf(v.x, v.y), fmaxf(v.z, v.w));
            #pragma unroll
            for (int o = 16; o > 0; o >>= 1) {
                vmin = fminf(vmin, __shfl_xor_sync(0xffffffffu, vmin, o));
                vmax = fmaxf(vmax, __shfl_xor_sync(0xffffffffu, vmax, o));
            }
            if (lane == 0) { red_min[wid] = vmin; red_max[wid] = vmax; }
            __syncthreads();

            if (wid == 0) {
                float m0 = (lane < 16) ? red_min[lane] :  3.4e38f;
                float m1 = (lane < 16) ? red_max[lane] : -3.4e38f;
                #pragma unroll
                for (int o = 8; o > 0; o >>= 1) {
                    m0 = fminf(m0, __shfl_xor_sync(0xffffffffu, m0, o));
                    m1 = fmaxf(m1, __shfl_xor_sync(0xffffffffu, m1, o));
                }
                if (lane == 0) {
                    sh_mn  = m0;
                    sh_inv = 2.0f / (m1 - m0 + EPS);
                }
            }
            __syncthreads();

            const float mn  = sh_mn;
            const float inv = sh_inv;

            s4.x = fminf(fmaxf((v.x - mn) * inv - 1.0f, -1.0f + EPS), 1.0f - EPS);
            s4.y = fminf(fmaxf((v.y - mn) * inv - 1.0f, -1.0f + EPS), 1.0f - EPS);
            s4.z = fminf(fmaxf((v.z - mn) * inv - 1.0f, -1.0f + EPS), 1.0f - EPS);
            s4.w = fminf(fmaxf((v.w - mn) * inv - 1.0f, -1.0f + EPS), 1.0f - EPS);
            r4.x = sqrtf(fmaxf(1.0f - s4.x * s4.x, 0.0f));
            r4.y = sqrtf(fmaxf(1.0f - s4.y * s4.y, 0.0f));
            r4.z = sqrtf(fmaxf(1.0f - s4.z * s4.z, 0.0f));
            r4.w = sqrtf(fmaxf(1.0f - s4.w * s4.w, 0.0f));
        }

        // ---- publish this tile's 16 (si,ri) pairs ----
        __syncthreads();                      // prior tile's reads done
        const int rel = t * 4 - i0;
        if (rel >= 0 && rel < ROWS_PER_BLK) {
            sh_si[rel + 0] = s4.x;  sh_ri[rel + 0] = r4.x;
            sh_si[rel + 1] = s4.y;  sh_ri[rel + 1] = r4.y;
            sh_si[rel + 2] = s4.z;  sh_ri[rel + 2] = r4.z;
            sh_si[rel + 3] = s4.w;  sh_ri[rel + 3] = r4.w;
        }
        __syncthreads();

        float* base = out + (size_t)b * L * L + (size_t)i0 * L;

        #pragma unroll
        for (int h = 0; h < 2; h++) {
            float si[8], ri[8];
            #pragma unroll
            for (int k = 0; k < 8; k++) {
                si[k] = sh_si[h * 8 + k];
                ri[k] = sh_ri[h * 8 + k];
            }
            #pragma unroll
            for (int k = 0; k < 8; k++) {
                float4 o;
                o.x = si[k] * s4.x - ri[k] * r4.x;
                o.y = si[k] * s4.y - ri[k] * r4.y;
                o.z = si[k] * s4.z - ri[k] * r4.z;
                o.w = si[k] * s4.w - ri[k] * r4.w;
                __stcs(reinterpret_cast<float4*>(base + (size_t)(h * 8 + k) * L) + t, o);
            }
        }
    }
}

extern "C" void kernel_launch(void* const* d_in, const int* in_sizes, int n_in,
                              void* d_out, int out_size) {
    const float* x = (const float*)d_in[0];
    float* out = (float*)d_out;

    gaf_persist_kernel<<<GRID, THREADS>>>(x, out);
}

// round 6
// speedup vs baseline: 1.0775x; 1.0775x over previous
#include <cuda_runtime.h>

#define B 16
#define L 2048
#define EPS 1e-8f
#define ROWS_PER_BLK 16
#define THREADS 256

// Fused GAF: out[b][i][j] = s_i*s_j - r_i*r_j, s = clipped minmax scale of x
// (= cos(arccos(s))), r = sqrt(1-s^2) (= sin). No trig in the hot path.
// One block = 16 consecutive i-rows of one batch, 256 threads, each thread
// owns 8 j-columns (two float4 segments) -> 32 independent STG.128 per thread.
__global__ void __launch_bounds__(THREADS) gaf_fused_kernel(
    const float* __restrict__ x, float* __restrict__ out) {
    const int b  = blockIdx.y;
    const int i0 = blockIdx.x * ROWS_PER_BLK;
    const int t  = threadIdx.x;
    const int lane = t & 31;
    const int wid  = t >> 5;                 // 8 warps

    __shared__ float red_min[8], red_max[8];
    __shared__ float sh_mn, sh_inv;
    __shared__ float sh_si[ROWS_PER_BLK], sh_ri[ROWS_PER_BLK];

    // ---- load x row: 256 threads x 2 float4 = 2048 elems ----
    const float4* xv = reinterpret_cast<const float4*>(x + b * L);
    const float4 v_lo = xv[t];
    const float4 v_hi = xv[t + 256];

    float vmin = fminf(fminf(fminf(v_lo.x, v_lo.y), fminf(v_lo.z, v_lo.w)),
                       fminf(fminf(v_hi.x, v_hi.y), fminf(v_hi.z, v_hi.w)));
    float vmax = fmaxf(fmaxf(fmaxf(v_lo.x, v_lo.y), fmaxf(v_lo.z, v_lo.w)),
                       fmaxf(fmaxf(v_hi.x, v_hi.y), fmaxf(v_hi.z, v_hi.w)));
    #pragma unroll
    for (int o = 16; o > 0; o >>= 1) {
        vmin = fminf(vmin, __shfl_xor_sync(0xffffffffu, vmin, o));
        vmax = fmaxf(vmax, __shfl_xor_sync(0xffffffffu, vmax, o));
    }
    if (lane == 0) { red_min[wid] = vmin; red_max[wid] = vmax; }
    __syncthreads();

    if (wid == 0) {
        float m0 = (lane < 8) ? red_min[lane] :  3.4e38f;
        float m1 = (lane < 8) ? red_max[lane] : -3.4e38f;
        #pragma unroll
        for (int o = 4; o > 0; o >>= 1) {
            m0 = fminf(m0, __shfl_xor_sync(0xffffffffu, m0, o));
            m1 = fmaxf(m1, __shfl_xor_sync(0xffffffffu, m1, o));
        }
        if (lane == 0) {
            sh_mn  = m0;
            sh_inv = 2.0f / (m1 - m0 + EPS);
        }
    }
    __syncthreads();

    const float mn  = sh_mn;
    const float inv = sh_inv;

    // ---- own 8 j-values in registers ----
    float s[8], r[8];
    {
        const float vv[8] = {v_lo.x, v_lo.y, v_lo.z, v_lo.w,
                             v_hi.x, v_hi.y, v_hi.z, v_hi.w};
        #pragma unroll
        for (int k = 0; k < 8; k++) {
            float sv = fminf(fmaxf((vv[k] - mn) * inv - 1.0f, -1.0f + EPS), 1.0f - EPS);
            s[k] = sv;
            r[k] = sqrtf(fmaxf(1.0f - sv * sv, 0.0f));
        }
    }

    // ---- publish the 16 (si,ri) pairs this block needs ----
    // lo segment covers elems 4t..4t+3; hi segment covers 1024+4t..1024+4t+3
    {
        const int rel0 = t * 4 - i0;
        if (rel0 >= 0 && rel0 < ROWS_PER_BLK) {
            #pragma unroll
            for (int c = 0; c < 4; c++) { sh_si[rel0 + c] = s[c]; sh_ri[rel0 + c] = r[c]; }
        }
        const int rel1 = t * 4 + 1024 - i0;
        if (rel1 >= 0 && rel1 < ROWS_PER_BLK) {
            #pragma unroll
            for (int c = 0; c < 4; c++) { sh_si[rel1 + c] = s[4 + c]; sh_ri[rel1 + c] = r[4 + c]; }
        }
    }
    __syncthreads();

    float* base = out + (size_t)b * L * L + (size_t)i0 * L;

    // ---- 16 rows x 2 segments, fully unrolled in 4-row groups ----
    #pragma unroll
    for (int h = 0; h < 4; h++) {
        float si[4], ri[4];
        #pragma unroll
        for (int k = 0; k < 4; k++) {
            si[k] = sh_si[h * 4 + k];
            ri[k] = sh_ri[h * 4 + k];
        }
        #pragma unroll
        for (int k = 0; k < 4; k++) {
            float4 o_lo, o_hi;
            o_lo.x = si[k] * s[0] - ri[k] * r[0];
            o_lo.y = si[k] * s[1] - ri[k] * r[1];
            o_lo.z = si[k] * s[2] - ri[k] * r[2];
            o_lo.w = si[k] * s[3] - ri[k] * r[3];
            o_hi.x = si[k] * s[4] - ri[k] * r[4];
            o_hi.y = si[k] * s[5] - ri[k] * r[5];
            o_hi.z = si[k] * s[6] - ri[k] * r[6];
            o_hi.w = si[k] * s[7] - ri[k] * r[7];
            float4* rowp = reinterpret_cast<float4*>(base + (size_t)(h * 4 + k) * L);
            __stcs(rowp + t, o_lo);
            __stcs(rowp + t + 256, o_hi);
        }
    }
}

extern "C" void kernel_launch(void* const* d_in, const int* in_sizes, int n_in,
                              void* d_out, int out_size) {
    const float* x = (const float*)d_in[0];
    float* out = (float*)d_out;

    dim3 grid(L / ROWS_PER_BLK, B);
    gaf_fused_kernel<<<grid, THREADS>>>(x, out);
}

// round 7
// speedup vs baseline: 1.0959x; 1.0171x over previous
#include <cuda_runtime.h>

#define B 16
#define L 2048
#define EPS 1e-8f
#define ROWS_PER_BLK 16
#define THREADS 512

// Fused GAF: out[b][i][j] = s_i*s_j - r_i*r_j, s = clipped minmax scale of x
// (= cos(arccos(s))), r = sqrt(1-s^2) (= sin). No trig in the hot path.
// One block = 16 consecutive i-rows of one batch, 512 threads.
// Thread t owns j-columns (t&255)*8..+7; the two 256-thread halves cover
// even/odd rows of each row pair. Stores are sm_103a 256-bit st.global.v8.f32
// (STG.256) with .cs streaming hint — half the LSU ops per byte vs STG.128.
__global__ void __launch_bounds__(THREADS, 3) gaf_fused_kernel(
    const float* __restrict__ x, float* __restrict__ out) {
    const int b    = blockIdx.y;
    const int i0   = blockIdx.x * ROWS_PER_BLK;
    const int t    = threadIdx.x;
    const int lane = t & 31;
    const int wid  = t >> 5;                 // 16 warps
    const int cseg = t & 255;                // column segment owner id
    const int rhalf = t >> 8;                // 0: even rows, 1: odd rows

    __shared__ float red_min[16], red_max[16];
    __shared__ float sh_mn, sh_inv;
    __shared__ float sh_si[ROWS_PER_BLK], sh_ri[ROWS_PER_BLK];

    // ---- load own 8 x-values (both halves load the same columns; the
    //      duplicate work is free, the reduction tolerates duplicates) ----
    const float4* xv = reinterpret_cast<const float4*>(x + b * L);
    const float4 v_lo = xv[cseg * 2];
    const float4 v_hi = xv[cseg * 2 + 1];

    float vmin = fminf(fminf(fminf(v_lo.x, v_lo.y), fminf(v_lo.z, v_lo.w)),
                       fminf(fminf(v_hi.x, v_hi.y), fminf(v_hi.z, v_hi.w)));
    float vmax = fmaxf(fmaxf(fmaxf(v_lo.x, v_lo.y), fmaxf(v_lo.z, v_lo.w)),
                       fmaxf(fmaxf(v_hi.x, v_hi.y), fmaxf(v_hi.z, v_hi.w)));
    #pragma unroll
    for (int o = 16; o > 0; o >>= 1) {
        vmin = fminf(vmin, __shfl_xor_sync(0xffffffffu, vmin, o));
        vmax = fmaxf(vmax, __shfl_xor_sync(0xffffffffu, vmax, o));
    }
    if (lane == 0) { red_min[wid] = vmin; red_max[wid] = vmax; }
    __syncthreads();

    if (wid == 0) {
        float m0 = (lane < 16) ? red_min[lane] :  3.4e38f;
        float m1 = (lane < 16) ? red_max[lane] : -3.4e38f;
        #pragma unroll
        for (int o = 8; o > 0; o >>= 1) {
            m0 = fminf(m0, __shfl_xor_sync(0xffffffffu, m0, o));
            m1 = fmaxf(m1, __shfl_xor_sync(0xffffffffu, m1, o));
        }
        if (lane == 0) {
            sh_mn  = m0;
            sh_inv = 2.0f / (m1 - m0 + EPS);
        }
    }
    __syncthreads();

    const float mn  = sh_mn;
    const float inv = sh_inv;

    // ---- own 8 j-values (s = cos phi, r = sin phi) in registers ----
    float s[8], r[8];
    {
        const float vv[8] = {v_lo.x, v_lo.y, v_lo.z, v_lo.w,
                             v_hi.x, v_hi.y, v_hi.z, v_hi.w};
        #pragma unroll
        for (int k = 0; k < 8; k++) {
            float sv = fminf(fmaxf((vv[k] - mn) * inv - 1.0f, -1.0f + EPS), 1.0f - EPS);
            s[k] = sv;
            r[k] = sqrtf(fmaxf(1.0f - sv * sv, 0.0f));
        }
    }

    // ---- publish the 16 (si,ri) pairs this block needs ----
    // element i0+e is owned by column-segment (i0+e)>>3; i0 is a multiple of
    // 16, so exactly segments i0/8 and i0/8+1 publish (only from half 0).
    if (rhalf == 0) {
        const int rel = cseg * 8 - i0;        // -? .. 15 when owner
        if (rel == 0 || rel == 8) {
            #pragma unroll
            for (int c = 0; c < 8; c++) { sh_si[rel + c] = s[c]; sh_ri[rel + c] = r[c]; }
        }
    }
    __syncthreads();

    float* base = out + (size_t)b * L * L + (size_t)i0 * L + cseg * 8;

    // ---- 8 row-pairs, one 256-bit streaming store each, fully unrolled ----
    #pragma unroll
    for (int p = 0; p < 8; p++) {
        const int row = p * 2 + rhalf;
        const float si = sh_si[row];
        const float ri = sh_ri[row];
        float o0 = si * s[0] - ri * r[0];
        float o1 = si * s[1] - ri * r[1];
        float o2 = si * s[2] - ri * r[2];
        float o3 = si * s[3] - ri * r[3];
        float o4 = si * s[4] - ri * r[4];
        float o5 = si * s[5] - ri * r[5];
        float o6 = si * s[6] - ri * r[6];
        float o7 = si * s[7] - ri * r[7];
        float* p256 = base + (size_t)row * L;   // 32B-aligned: base%32==0
        asm volatile(
            "st.global.cs.v8.f32 [%0], {%1, %2, %3, %4, %5, %6, %7, %8};"
            :: "l"(p256),
               "f"(o0), "f"(o1), "f"(o2), "f"(o3),
               "f"(o4), "f"(o5), "f"(o6), "f"(o7)
            : "memory");
    }
}

extern "C" void kernel_launch(void* const* d_in, const int* in_sizes, int n_in,
                              void* d_out, int out_size) {
    const float* x = (const float*)d_in[0];
    float* out = (float*)d_out;

    dim3 grid(L / ROWS_PER_BLK, B);
    gaf_fused_kernel<<<grid, THREADS>>>(x, out);
}